// round 13
// baseline (speedup 1.0000x reference)
#include <cuda_runtime.h>

// Problem constants (fixed by the reference)
#define NN 50000      // nodes
#define EE 800000     // edges
#define GG 32         // graphs
#define CC 16         // classes
#define NEG_SLOPE 0.2f
#define BN_EPS 1e-5f

// ---------------------------------------------------------------------------
// Scratch (static device globals; no allocation allowed)
// ---------------------------------------------------------------------------
__device__ float g_buf0[NN * 128];   // layer activations (ping)
__device__ float g_buf1[NN * 128];   // layer activations (pong)
__device__ float g_z[NN * 128];      // z = h @ W for current layer
__device__ float g_score[EE * 2];    // per-edge per-head score, then exp(score-max)
__device__ float g_denom[NN * 2];    // softmax denominators per dst,head
__device__ int   g_maxi[NN * 2];     // ordered-int encoded segment max per dst,head
__device__ float g_outf[NN * 32];    // final layer output [N,2,16]
__device__ float g_pooled[GG * CC];  // graph-pooled logits

// ---------------------------------------------------------------------------
// Helpers
// ---------------------------------------------------------------------------
__device__ __forceinline__ int f2o(float f) {           // order-preserving float->int
    int i = __float_as_int(f);
    return i >= 0 ? i : (i ^ 0x7fffffff);
}
__device__ __forceinline__ float o2f(int i) {
    return __int_as_float(i >= 0 ? i : (i ^ 0x7fffffff));
}
__device__ __forceinline__ float lrelu(float x) { return x > 0.f ? x : NEG_SLOPE * x; }

// ---------------------------------------------------------------------------
// Tiled SGEMM: Z[nrows, NC] = act(A[nrows,128]) @ W[128, NC]
// 128 rows per block, 256 threads, K chunked by 32 through shared memory.
// NC=128 (CPT=8) for hidden layers, NC=32 (CPT=2) for the final projection.
// relu_in != 0 applies ReLU to A while loading (layer activation fusion).
// ---------------------------------------------------------------------------
template <int NC, int CPT>
__global__ void __launch_bounds__(256)
gemm_k128(const float* __restrict__ A, const float* __restrict__ W,
          float* __restrict__ Z, int nrows, int relu_in)
{
    __shared__ float hs[128][33];     // padded to kill bank conflicts on a-loads
    __shared__ float Ws[32][NC];

    const int t  = threadIdx.x;
    const int tx = t & 15;            // column group
    const int ty = t >> 4;            // row group
    const int rowBase = blockIdx.x * 128;

    float acc[8][CPT];
#pragma unroll
    for (int i = 0; i < 8; i++)
#pragma unroll
        for (int j = 0; j < CPT; j++) acc[i][j] = 0.f;

#pragma unroll
    for (int kc = 0; kc < 4; kc++) {
        // --- stage A chunk: rows [rowBase, rowBase+128), cols [kc*32, kc*32+32)
#pragma unroll
        for (int q = 0; q < 4; q++) {
            int idx = t + q * 256;          // float4 index in [0,1024)
            int e   = idx * 4;
            int r   = e >> 5;               // 0..127
            int c   = e & 31;               // 0,4,...,28
            int gr  = rowBase + r;
            float4 v = make_float4(0.f, 0.f, 0.f, 0.f);
            if (gr < nrows)
                v = *reinterpret_cast<const float4*>(A + (size_t)gr * 128 + kc * 32 + c);
            if (relu_in) {
                v.x = fmaxf(v.x, 0.f); v.y = fmaxf(v.y, 0.f);
                v.z = fmaxf(v.z, 0.f); v.w = fmaxf(v.w, 0.f);
            }
            hs[r][c + 0] = v.x; hs[r][c + 1] = v.y;
            hs[r][c + 2] = v.z; hs[r][c + 3] = v.w;
        }
        // --- stage W chunk: rows [kc*32, kc*32+32), all NC cols
        constexpr int WV = (32 * NC) / 4;
#pragma unroll
        for (int idx = t; idx < WV; idx += 256) {
            int e = idx * 4;
            int r = e / NC;
            int c = e % NC;
            float4 v = *reinterpret_cast<const float4*>(W + (size_t)(kc * 32 + r) * NC + c);
            *reinterpret_cast<float4*>(&Ws[r][c]) = v;
        }
        __syncthreads();

#pragma unroll
        for (int k = 0; k < 32; k++) {
            float a[8], b[CPT];
#pragma unroll
            for (int i = 0; i < 8; i++) a[i] = hs[ty + 16 * i][k];
#pragma unroll
            for (int j = 0; j < CPT; j++) b[j] = Ws[k][tx + 16 * j];
#pragma unroll
            for (int i = 0; i < 8; i++)
#pragma unroll
                for (int j = 0; j < CPT; j++)
                    acc[i][j] = fmaf(a[i], b[j], acc[i][j]);
        }
        __syncthreads();
    }

#pragma unroll
    for (int i = 0; i < 8; i++) {
        int gr = rowBase + ty + 16 * i;
        if (gr < nrows) {
#pragma unroll
            for (int j = 0; j < CPT; j++)
                Z[(size_t)gr * NC + tx + 16 * j] = acc[i][j];
        }
    }
}

// ---------------------------------------------------------------------------
// Per-layer init: zero accumulation buffer, zero denominators, -inf segment max
// ---------------------------------------------------------------------------
__global__ void init_k(float* __restrict__ out, int nout, int zero_pooled)
{
    int idx = blockIdx.x * blockDim.x + threadIdx.x;
    if (idx < nout) out[idx] = 0.f;
    if (idx < NN * 2) { g_denom[idx] = 0.f; g_maxi[idx] = (int)0x80000000; }
    if (zero_pooled && idx < GG * CC) g_pooled[idx] = 0.f;
}

// ---------------------------------------------------------------------------
// Hidden layers (D=64, H=2): one warp per edge.
// Lanes 0..15 = head 0 dims, lanes 16..31 = head 1 dims (4 dims each).
// ---------------------------------------------------------------------------
__global__ void __launch_bounds__(256)
edge_score_128(const float* __restrict__ z, const int* __restrict__ src,
               const int* __restrict__ dst, const float* __restrict__ attn)
{
    int e = blockIdx.x * 8 + (threadIdx.x >> 5);
    if (e >= EE) return;
    int lane = threadIdx.x & 31;
    int s = __ldg(src + e), d = __ldg(dst + e);

    float4 zs = *reinterpret_cast<const float4*>(z + (size_t)s * 128 + lane * 4);
    float4 zd = *reinterpret_cast<const float4*>(z + (size_t)d * 128 + lane * 4);
    float4 at = *reinterpret_cast<const float4*>(attn + lane * 4);   // attn flat [128]

    float ex = lrelu(zs.x + zd.x);
    float ey = lrelu(zs.y + zd.y);
    float ez = lrelu(zs.z + zd.z);
    float ew = lrelu(zs.w + zd.w);
    float p = ex * at.x + ey * at.y + ez * at.z + ew * at.w;

    p += __shfl_xor_sync(0xffffffffu, p, 8);
    p += __shfl_xor_sync(0xffffffffu, p, 4);
    p += __shfl_xor_sync(0xffffffffu, p, 2);
    p += __shfl_xor_sync(0xffffffffu, p, 1);

    if ((lane & 15) == 0) {
        int h = lane >> 4;
        g_score[e * 2 + h] = p;
        atomicMax(&g_maxi[d * 2 + h], f2o(p));
    }
}

// exp(score - max) + denominator accumulation (shared by all layers)
__global__ void edge_exp(const int* __restrict__ dst)
{
    int idx = blockIdx.x * blockDim.x + threadIdx.x;
    if (idx >= EE * 2) return;
    int e = idx >> 1, h = idx & 1;
    int d = __ldg(dst + e);
    float m = o2f(g_maxi[d * 2 + h]);
    float a = __expf(g_score[idx] - m);
    g_score[idx] = a;
    atomicAdd(&g_denom[d * 2 + h], a);
}

__global__ void __launch_bounds__(256)
edge_aggr_128(const float* __restrict__ z, const int* __restrict__ src,
              const int* __restrict__ dst, float* __restrict__ out)
{
    int e = blockIdx.x * 8 + (threadIdx.x >> 5);
    if (e >= EE) return;
    int lane = threadIdx.x & 31;
    int s = __ldg(src + e), d = __ldg(dst + e);
    int h = lane >> 4;

    float den = g_denom[d * 2 + h];
    float alpha = g_score[e * 2 + h] / (den == 0.f ? 1.f : den);

    float4 zs = *reinterpret_cast<const float4*>(z + (size_t)s * 128 + lane * 4);
    float* o = out + (size_t)d * 128 + lane * 4;
    atomicAdd(o + 0, zs.x * alpha);
    atomicAdd(o + 1, zs.y * alpha);
    atomicAdd(o + 2, zs.z * alpha);
    atomicAdd(o + 3, zs.w * alpha);
}

// ---------------------------------------------------------------------------
// Final layer (C=16, H=2): one thread per (edge, head)
// ---------------------------------------------------------------------------
__global__ void edge_score_f(const float* __restrict__ z, const int* __restrict__ src,
                             const int* __restrict__ dst, const float* __restrict__ attnf)
{
    int idx = blockIdx.x * blockDim.x + threadIdx.x;
    if (idx >= EE * 2) return;
    int e = idx >> 1, h = idx & 1;
    int s = __ldg(src + e), d = __ldg(dst + e);

    const float4* zs = reinterpret_cast<const float4*>(z + (size_t)s * 32 + h * 16);
    const float4* zd = reinterpret_cast<const float4*>(z + (size_t)d * 32 + h * 16);
    const float4* at = reinterpret_cast<const float4*>(attnf + h * 16);

    float p = 0.f;
#pragma unroll
    for (int q = 0; q < 4; q++) {
        float4 a = zs[q], b = zd[q], w = at[q];
        p += lrelu(a.x + b.x) * w.x;
        p += lrelu(a.y + b.y) * w.y;
        p += lrelu(a.z + b.z) * w.z;
        p += lrelu(a.w + b.w) * w.w;
    }
    g_score[idx] = p;
    atomicMax(&g_maxi[d * 2 + h], f2o(p));
}

__global__ void edge_aggr_f(const float* __restrict__ z, const int* __restrict__ src,
                            const int* __restrict__ dst, float* __restrict__ outf)
{
    int idx = blockIdx.x * blockDim.x + threadIdx.x;
    if (idx >= EE * 2) return;
    int e = idx >> 1, h = idx & 1;
    int s = __ldg(src + e), d = __ldg(dst + e);

    float den = g_denom[d * 2 + h];
    float alpha = g_score[idx] / (den == 0.f ? 1.f : den);

    const float4* zs = reinterpret_cast<const float4*>(z + (size_t)s * 32 + h * 16);
    float* o = outf + (size_t)d * 32 + h * 16;
#pragma unroll
    for (int q = 0; q < 4; q++) {
        float4 v = zs[q];
        atomicAdd(o + q * 4 + 0, v.x * alpha);
        atomicAdd(o + q * 4 + 1, v.y * alpha);
        atomicAdd(o + q * 4 + 2, v.z * alpha);
        atomicAdd(o + q * 4 + 3, v.w * alpha);
    }
}

// Mean over heads + graph pooling (segment_sum by node_graph)
__global__ void pool_k(const float* __restrict__ outf, const int* __restrict__ ng)
{
    int idx = blockIdx.x * blockDim.x + threadIdx.x;
    if (idx >= NN * CC) return;
    int n = idx >> 4, c = idx & 15;
    float v = 0.5f * (outf[n * 32 + c] + outf[n * 32 + 16 + c]);
    atomicAdd(&g_pooled[__ldg(ng + n) * CC + c], v);
}

// ---------------------------------------------------------------------------
// Tiny MLP head: lin -> batchnorm(training stats) -> relu -> lin -> log_softmax
// Single block, 512 threads = (32 graphs x 16 classes).
// ---------------------------------------------------------------------------
__global__ void __launch_bounds__(512)
mlp_k(const float* __restrict__ w1, const float* __restrict__ gamma,
      const float* __restrict__ beta, const float* __restrict__ w2,
      float* __restrict__ out)
{
    __shared__ float P[GG][CC], H1[GG][CC], R[GG][CC], O[GG][CC];
    __shared__ float mu[CC], iv[CC];
    __shared__ float rm[GG], rl[GG];

    int t = threadIdx.x;
    int i = t >> 4, j = t & 15;

    P[i][j] = g_pooled[t];
    __syncthreads();

    float acc = 0.f;
#pragma unroll
    for (int k = 0; k < CC; k++) acc += P[i][k] * w1[k * CC + j];
    H1[i][j] = acc;
    __syncthreads();

    if (t < CC) {
        float m = 0.f;
        for (int r = 0; r < GG; r++) m += H1[r][t];
        m *= (1.f / GG);
        float v = 0.f;
        for (int r = 0; r < GG; r++) { float d = H1[r][t] - m; v += d * d; }
        v *= (1.f / GG);
        mu[t] = m;
        iv[t] = rsqrtf(v + BN_EPS);
    }
    __syncthreads();

    float hn = (H1[i][j] - mu[j]) * iv[j] * gamma[j] + beta[j];
    R[i][j] = fmaxf(hn, 0.f);
    __syncthreads();

    acc = 0.f;
#pragma unroll
    for (int k = 0; k < CC; k++) acc += R[i][k] * w2[k * CC + j];
    O[i][j] = acc;
    __syncthreads();

    if (j == 0) {
        float m = -1e30f;
        for (int k = 0; k < CC; k++) m = fmaxf(m, O[i][k]);
        float s = 0.f;
        for (int k = 0; k < CC; k++) s += __expf(O[i][k] - m);
        rm[i] = m;
        rl[i] = logf(s);
    }
    __syncthreads();

    out[t] = O[i][j] - rm[i] - rl[i];
}

// ---------------------------------------------------------------------------
// Host launch sequence (graph-capturable; kernel launches only)
// ---------------------------------------------------------------------------
extern "C" void kernel_launch(void* const* d_in, const int* in_sizes, int n_in,
                              void* d_out, int out_size)
{
    const float* feat  = (const float*)d_in[0];
    const float* W0    = (const float*)d_in[1];
    const float* attn0 = (const float*)d_in[2];
    const float* W1    = (const float*)d_in[3];
    const float* attn1 = (const float*)d_in[4];
    const float* W2    = (const float*)d_in[5];
    const float* attn2 = (const float*)d_in[6];
    const float* Wf    = (const float*)d_in[7];
    const float* attnf = (const float*)d_in[8];
    const float* mw1   = (const float*)d_in[9];
    const float* gam   = (const float*)d_in[10];
    const float* bet   = (const float*)d_in[11];
    const float* mw2   = (const float*)d_in[12];
    const int*   src   = (const int*)d_in[13];
    const int*   dst   = (const int*)d_in[14];
    const int*   ng    = (const int*)d_in[15];

    float *buf0, *buf1, *zbuf, *outf;
    cudaGetSymbolAddress((void**)&buf0, g_buf0);
    cudaGetSymbolAddress((void**)&buf1, g_buf1);
    cudaGetSymbolAddress((void**)&zbuf, g_z);
    cudaGetSymbolAddress((void**)&outf, g_outf);

    const int GEMM_BLOCKS = (NN + 127) / 128;          // 391
    const int EW_BLOCKS   = (EE + 7) / 8;              // warp-per-edge: 100000
    const int ET_BLOCKS   = (EE * 2 + 255) / 256;      // thread-per-(edge,head): 6250
    const int INIT_BLOCKS = (NN * 128 + 255) / 256;    // 25000
    const int INITF_BLOCKS= (NN * 32 + 255) / 256;     // 6250 (covers NN*2 too)
    const int POOL_BLOCKS = (NN * CC + 255) / 256;     // 3125

    // ---- layer 0: feat -> buf0
    gemm_k128<128, 8><<<GEMM_BLOCKS, 256>>>(feat, W0, zbuf, NN, 0);
    init_k<<<INIT_BLOCKS, 256>>>(buf0, NN * 128, 0);
    edge_score_128<<<EW_BLOCKS, 256>>>(zbuf, src, dst, attn0);
    edge_exp<<<ET_BLOCKS, 256>>>(dst);
    edge_aggr_128<<<EW_BLOCKS, 256>>>(zbuf, src, dst, buf0);

    // ---- layer 1: relu(buf0) -> buf1
    gemm_k128<128, 8><<<GEMM_BLOCKS, 256>>>(buf0, W1, zbuf, NN, 1);
    init_k<<<INIT_BLOCKS, 256>>>(buf1, NN * 128, 0);
    edge_score_128<<<EW_BLOCKS, 256>>>(zbuf, src, dst, attn1);
    edge_exp<<<ET_BLOCKS, 256>>>(dst);
    edge_aggr_128<<<EW_BLOCKS, 256>>>(zbuf, src, dst, buf1);

    // ---- layer 2: relu(buf1) -> buf0
    gemm_k128<128, 8><<<GEMM_BLOCKS, 256>>>(buf1, W2, zbuf, NN, 1);
    init_k<<<INIT_BLOCKS, 256>>>(buf0, NN * 128, 0);
    edge_score_128<<<EW_BLOCKS, 256>>>(zbuf, src, dst, attn2);
    edge_exp<<<ET_BLOCKS, 256>>>(dst);
    edge_aggr_128<<<EW_BLOCKS, 256>>>(zbuf, src, dst, buf0);

    // ---- final GAT layer: relu(buf0) @ Wf -> zf [N,32]; aggregate -> outf
    gemm_k128<32, 2><<<GEMM_BLOCKS, 256>>>(buf0, Wf, zbuf, NN, 1);
    init_k<<<INITF_BLOCKS, 256>>>(outf, NN * 32, 1);
    edge_score_f<<<ET_BLOCKS, 256>>>(zbuf, src, dst, attnf);
    edge_exp<<<ET_BLOCKS, 256>>>(dst);
    edge_aggr_f<<<ET_BLOCKS, 256>>>(zbuf, src, dst, outf);

    // ---- head: mean over heads, graph pooling, MLP+BN+log_softmax
    pool_k<<<POOL_BLOCKS, 256>>>(outf, ng);
    mlp_k<<<1, 512>>>(mw1, gam, bet, mw2, (float*)d_out);

    (void)in_sizes; (void)n_in; (void)out_size;
}

// round 14
// speedup vs baseline: 1.0069x; 1.0069x over previous
#include <cuda_runtime.h>

// Problem constants (fixed by the reference)
#define NN 50000      // nodes
#define EE 800000     // edges
#define GG 32         // graphs
#define CC 16         // classes
#define NEG_SLOPE 0.2f
#define BN_EPS 1e-5f

// ---------------------------------------------------------------------------
// Scratch (static device globals; no allocation allowed)
// ---------------------------------------------------------------------------
__device__ float g_buf0[NN * 128];   // layer activations (ping)
__device__ float g_buf1[NN * 128];   // layer activations (pong)
__device__ float g_z[NN * 128];      // z = h @ W for current layer
__device__ float g_score[EE * 2];    // per-edge per-head score, then exp(score-max)
__device__ float g_denom[NN * 2];    // softmax denominators per dst,head
__device__ int   g_maxi[NN * 2];     // ordered-int encoded segment max per dst,head
__device__ float g_outf[NN * 32];    // final layer output [N,2,16]
__device__ float g_pooled[GG * CC];  // graph-pooled logits

// ---------------------------------------------------------------------------
// Helpers
// ---------------------------------------------------------------------------
__device__ __forceinline__ int f2o(float f) {           // order-preserving float->int
    int i = __float_as_int(f);
    return i >= 0 ? i : (i ^ 0x7fffffff);
}
__device__ __forceinline__ float o2f(int i) {
    return __int_as_float(i >= 0 ? i : (i ^ 0x7fffffff));
}
__device__ __forceinline__ float lrelu(float x) { return x > 0.f ? x : NEG_SLOPE * x; }

// ---------------------------------------------------------------------------
// Tiled SGEMM: Z[nrows, NC] = act(A[nrows,128]) @ W[128, NC]
// 128 rows per block, 256 threads, K chunked by 32 through shared memory.
// NC=128 (CPT=8) for hidden layers, NC=32 (CPT=2) for the final projection.
// relu_in != 0 applies ReLU to A while loading (layer activation fusion).
// ---------------------------------------------------------------------------
template <int NC, int CPT>
__global__ void __launch_bounds__(256)
gemm_k128(const float* __restrict__ A, const float* __restrict__ W,
          float* __restrict__ Z, int nrows, int relu_in)
{
    __shared__ float hs[128][33];     // padded to kill bank conflicts on a-loads
    __shared__ float Ws[32][NC];

    const int t  = threadIdx.x;
    const int tx = t & 15;            // column group
    const int ty = t >> 4;            // row group
    const int rowBase = blockIdx.x * 128;

    float acc[8][CPT];
#pragma unroll
    for (int i = 0; i < 8; i++)
#pragma unroll
        for (int j = 0; j < CPT; j++) acc[i][j] = 0.f;

#pragma unroll
    for (int kc = 0; kc < 4; kc++) {
        // --- stage A chunk: rows [rowBase, rowBase+128), cols [kc*32, kc*32+32)
#pragma unroll
        for (int q = 0; q < 4; q++) {
            int idx = t + q * 256;          // float4 index in [0,1024)
            int e   = idx * 4;
            int r   = e >> 5;               // 0..127
            int c   = e & 31;               // 0,4,...,28
            int gr  = rowBase + r;
            float4 v = make_float4(0.f, 0.f, 0.f, 0.f);
            if (gr < nrows)
                v = *reinterpret_cast<const float4*>(A + (size_t)gr * 128 + kc * 32 + c);
            if (relu_in) {
                v.x = fmaxf(v.x, 0.f); v.y = fmaxf(v.y, 0.f);
                v.z = fmaxf(v.z, 0.f); v.w = fmaxf(v.w, 0.f);
            }
            hs[r][c + 0] = v.x; hs[r][c + 1] = v.y;
            hs[r][c + 2] = v.z; hs[r][c + 3] = v.w;
        }
        // --- stage W chunk: rows [kc*32, kc*32+32), all NC cols
        constexpr int WV = (32 * NC) / 4;
#pragma unroll
        for (int idx = t; idx < WV; idx += 256) {
            int e = idx * 4;
            int r = e / NC;
            int c = e % NC;
            float4 v = *reinterpret_cast<const float4*>(W + (size_t)(kc * 32 + r) * NC + c);
            *reinterpret_cast<float4*>(&Ws[r][c]) = v;
        }
        __syncthreads();

#pragma unroll
        for (int k = 0; k < 32; k++) {
            float a[8], b[CPT];
#pragma unroll
            for (int i = 0; i < 8; i++) a[i] = hs[ty + 16 * i][k];
#pragma unroll
            for (int j = 0; j < CPT; j++) b[j] = Ws[k][tx + 16 * j];
#pragma unroll
            for (int i = 0; i < 8; i++)
#pragma unroll
                for (int j = 0; j < CPT; j++)
                    acc[i][j] = fmaf(a[i], b[j], acc[i][j]);
        }
        __syncthreads();
    }

#pragma unroll
    for (int i = 0; i < 8; i++) {
        int gr = rowBase + ty + 16 * i;
        if (gr < nrows) {
#pragma unroll
            for (int j = 0; j < CPT; j++)
                Z[(size_t)gr * NC + tx + 16 * j] = acc[i][j];
        }
    }
}

// ---------------------------------------------------------------------------
// Per-layer init: zero accumulation buffer, zero denominators, -inf segment max
// ---------------------------------------------------------------------------
__global__ void init_k(float* __restrict__ out, int nout, int zero_pooled)
{
    int idx = blockIdx.x * blockDim.x + threadIdx.x;
    if (idx < nout) out[idx] = 0.f;
    if (idx < NN * 2) { g_denom[idx] = 0.f; g_maxi[idx] = (int)0x80000000; }
    if (zero_pooled && idx < GG * CC) g_pooled[idx] = 0.f;
}

// ---------------------------------------------------------------------------
// Hidden layers (D=64, H=2): one warp per edge.
// Lanes 0..15 = head 0 dims, lanes 16..31 = head 1 dims (4 dims each).
// ---------------------------------------------------------------------------
__global__ void __launch_bounds__(256)
edge_score_128(const float* __restrict__ z, const int* __restrict__ src,
               const int* __restrict__ dst, const float* __restrict__ attn)
{
    int e = blockIdx.x * 8 + (threadIdx.x >> 5);
    if (e >= EE) return;
    int lane = threadIdx.x & 31;
    int s = __ldg(src + e), d = __ldg(dst + e);

    float4 zs = *reinterpret_cast<const float4*>(z + (size_t)s * 128 + lane * 4);
    float4 zd = *reinterpret_cast<const float4*>(z + (size_t)d * 128 + lane * 4);
    float4 at = *reinterpret_cast<const float4*>(attn + lane * 4);   // attn flat [128]

    float ex = lrelu(zs.x + zd.x);
    float ey = lrelu(zs.y + zd.y);
    float ez = lrelu(zs.z + zd.z);
    float ew = lrelu(zs.w + zd.w);
    float p = ex * at.x + ey * at.y + ez * at.z + ew * at.w;

    p += __shfl_xor_sync(0xffffffffu, p, 8);
    p += __shfl_xor_sync(0xffffffffu, p, 4);
    p += __shfl_xor_sync(0xffffffffu, p, 2);
    p += __shfl_xor_sync(0xffffffffu, p, 1);

    if ((lane & 15) == 0) {
        int h = lane >> 4;
        g_score[e * 2 + h] = p;
        atomicMax(&g_maxi[d * 2 + h], f2o(p));
    }
}

// exp(score - max) + denominator accumulation (shared by all layers)
__global__ void edge_exp(const int* __restrict__ dst)
{
    int idx = blockIdx.x * blockDim.x + threadIdx.x;
    if (idx >= EE * 2) return;
    int e = idx >> 1, h = idx & 1;
    int d = __ldg(dst + e);
    float m = o2f(g_maxi[d * 2 + h]);
    float a = __expf(g_score[idx] - m);
    g_score[idx] = a;
    atomicAdd(&g_denom[d * 2 + h], a);
}

__global__ void __launch_bounds__(256)
edge_aggr_128(const float* __restrict__ z, const int* __restrict__ src,
              const int* __restrict__ dst, float* __restrict__ out)
{
    int e = blockIdx.x * 8 + (threadIdx.x >> 5);
    if (e >= EE) return;
    int lane = threadIdx.x & 31;
    int s = __ldg(src + e), d = __ldg(dst + e);
    int h = lane >> 4;

    float den = g_denom[d * 2 + h];
    float alpha = g_score[e * 2 + h] / (den == 0.f ? 1.f : den);

    float4 zs = *reinterpret_cast<const float4*>(z + (size_t)s * 128 + lane * 4);
    float* o = out + (size_t)d * 128 + lane * 4;
    atomicAdd(o + 0, zs.x * alpha);
    atomicAdd(o + 1, zs.y * alpha);
    atomicAdd(o + 2, zs.z * alpha);
    atomicAdd(o + 3, zs.w * alpha);
}

// ---------------------------------------------------------------------------
// Final layer (C=16, H=2): one thread per (edge, head)
// ---------------------------------------------------------------------------
__global__ void edge_score_f(const float* __restrict__ z, const int* __restrict__ src,
                             const int* __restrict__ dst, const float* __restrict__ attnf)
{
    int idx = blockIdx.x * blockDim.x + threadIdx.x;
    if (idx >= EE * 2) return;
    int e = idx >> 1, h = idx & 1;
    int s = __ldg(src + e), d = __ldg(dst + e);

    const float4* zs = reinterpret_cast<const float4*>(z + (size_t)s * 32 + h * 16);
    const float4* zd = reinterpret_cast<const float4*>(z + (size_t)d * 32 + h * 16);
    const float4* at = reinterpret_cast<const float4*>(attnf + h * 16);

    float p = 0.f;
#pragma unroll
    for (int q = 0; q < 4; q++) {
        float4 a = zs[q], b = zd[q], w = at[q];
        p += lrelu(a.x + b.x) * w.x;
        p += lrelu(a.y + b.y) * w.y;
        p += lrelu(a.z + b.z) * w.z;
        p += lrelu(a.w + b.w) * w.w;
    }
    g_score[idx] = p;
    atomicMax(&g_maxi[d * 2 + h], f2o(p));
}

__global__ void edge_aggr_f(const float* __restrict__ z, const int* __restrict__ src,
                            const int* __restrict__ dst, float* __restrict__ outf)
{
    int idx = blockIdx.x * blockDim.x + threadIdx.x;
    if (idx >= EE * 2) return;
    int e = idx >> 1, h = idx & 1;
    int s = __ldg(src + e), d = __ldg(dst + e);

    float den = g_denom[d * 2 + h];
    float alpha = g_score[idx] / (den == 0.f ? 1.f : den);

    const float4* zs = reinterpret_cast<const float4*>(z + (size_t)s * 32 + h * 16);
    float* o = outf + (size_t)d * 32 + h * 16;
#pragma unroll
    for (int q = 0; q < 4; q++) {
        float4 v = zs[q];
        atomicAdd(o + q * 4 + 0, v.x * alpha);
        atomicAdd(o + q * 4 + 1, v.y * alpha);
        atomicAdd(o + q * 4 + 2, v.z * alpha);
        atomicAdd(o + q * 4 + 3, v.w * alpha);
    }
}

// Mean over heads + graph pooling (segment_sum by node_graph)
__global__ void pool_k(const float* __restrict__ outf, const int* __restrict__ ng)
{
    int idx = blockIdx.x * blockDim.x + threadIdx.x;
    if (idx >= NN * CC) return;
    int n = idx >> 4, c = idx & 15;
    float v = 0.5f * (outf[n * 32 + c] + outf[n * 32 + 16 + c]);
    atomicAdd(&g_pooled[__ldg(ng + n) * CC + c], v);
}

// ---------------------------------------------------------------------------
// Tiny MLP head: lin -> batchnorm(training stats) -> relu -> lin -> log_softmax
// Single block, 512 threads = (32 graphs x 16 classes).
// ---------------------------------------------------------------------------
__global__ void __launch_bounds__(512)
mlp_k(const float* __restrict__ w1, const float* __restrict__ gamma,
      const float* __restrict__ beta, const float* __restrict__ w2,
      float* __restrict__ out)
{
    __shared__ float P[GG][CC], H1[GG][CC], R[GG][CC], O[GG][CC];
    __shared__ float mu[CC], iv[CC];
    __shared__ float rm[GG], rl[GG];

    int t = threadIdx.x;
    int i = t >> 4, j = t & 15;

    P[i][j] = g_pooled[t];
    __syncthreads();

    float acc = 0.f;
#pragma unroll
    for (int k = 0; k < CC; k++) acc += P[i][k] * w1[k * CC + j];
    H1[i][j] = acc;
    __syncthreads();

    if (t < CC) {
        float m = 0.f;
        for (int r = 0; r < GG; r++) m += H1[r][t];
        m *= (1.f / GG);
        float v = 0.f;
        for (int r = 0; r < GG; r++) { float d = H1[r][t] - m; v += d * d; }
        v *= (1.f / GG);
        mu[t] = m;
        iv[t] = rsqrtf(v + BN_EPS);
    }
    __syncthreads();

    float hn = (H1[i][j] - mu[j]) * iv[j] * gamma[j] + beta[j];
    R[i][j] = fmaxf(hn, 0.f);
    __syncthreads();

    acc = 0.f;
#pragma unroll
    for (int k = 0; k < CC; k++) acc += R[i][k] * w2[k * CC + j];
    O[i][j] = acc;
    __syncthreads();

    if (j == 0) {
        float m = -1e30f;
        for (int k = 0; k < CC; k++) m = fmaxf(m, O[i][k]);
        float s = 0.f;
        for (int k = 0; k < CC; k++) s += __expf(O[i][k] - m);
        rm[i] = m;
        rl[i] = logf(s);
    }
    __syncthreads();

    out[t] = O[i][j] - rm[i] - rl[i];
}

// ---------------------------------------------------------------------------
// Host launch sequence (graph-capturable; kernel launches only)
// ---------------------------------------------------------------------------
extern "C" void kernel_launch(void* const* d_in, const int* in_sizes, int n_in,
                              void* d_out, int out_size)
{
    const float* feat  = (const float*)d_in[0];
    const float* W0    = (const float*)d_in[1];
    const float* attn0 = (const float*)d_in[2];
    const float* W1    = (const float*)d_in[3];
    const float* attn1 = (const float*)d_in[4];
    const float* W2    = (const float*)d_in[5];
    const float* attn2 = (const float*)d_in[6];
    const float* Wf    = (const float*)d_in[7];
    const float* attnf = (const float*)d_in[8];
    const float* mw1   = (const float*)d_in[9];
    const float* gam   = (const float*)d_in[10];
    const float* bet   = (const float*)d_in[11];
    const float* mw2   = (const float*)d_in[12];
    const int*   src   = (const int*)d_in[13];
    const int*   dst   = (const int*)d_in[14];
    const int*   ng    = (const int*)d_in[15];

    float *buf0, *buf1, *zbuf, *outf;
    cudaGetSymbolAddress((void**)&buf0, g_buf0);
    cudaGetSymbolAddress((void**)&buf1, g_buf1);
    cudaGetSymbolAddress((void**)&zbuf, g_z);
    cudaGetSymbolAddress((void**)&outf, g_outf);

    const int GEMM_BLOCKS = (NN + 127) / 128;          // 391
    const int EW_BLOCKS   = (EE + 7) / 8;              // warp-per-edge: 100000
    const int ET_BLOCKS   = (EE * 2 + 255) / 256;      // thread-per-(edge,head): 6250
    const int INIT_BLOCKS = (NN * 128 + 255) / 256;    // 25000
    const int INITF_BLOCKS= (NN * 32 + 255) / 256;     // 6250 (covers NN*2 too)
    const int POOL_BLOCKS = (NN * CC + 255) / 256;     // 3125

    // ---- layer 0: feat -> buf0
    gemm_k128<128, 8><<<GEMM_BLOCKS, 256>>>(feat, W0, zbuf, NN, 0);
    init_k<<<INIT_BLOCKS, 256>>>(buf0, NN * 128, 0);
    edge_score_128<<<EW_BLOCKS, 256>>>(zbuf, src, dst, attn0);
    edge_exp<<<ET_BLOCKS, 256>>>(dst);
    edge_aggr_128<<<EW_BLOCKS, 256>>>(zbuf, src, dst, buf0);

    // ---- layer 1: relu(buf0) -> buf1
    gemm_k128<128, 8><<<GEMM_BLOCKS, 256>>>(buf0, W1, zbuf, NN, 1);
    init_k<<<INIT_BLOCKS, 256>>>(buf1, NN * 128, 0);
    edge_score_128<<<EW_BLOCKS, 256>>>(zbuf, src, dst, attn1);
    edge_exp<<<ET_BLOCKS, 256>>>(dst);
    edge_aggr_128<<<EW_BLOCKS, 256>>>(zbuf, src, dst, buf1);

    // ---- layer 2: relu(buf1) -> buf0
    gemm_k128<128, 8><<<GEMM_BLOCKS, 256>>>(buf1, W2, zbuf, NN, 1);
    init_k<<<INIT_BLOCKS, 256>>>(buf0, NN * 128, 0);
    edge_score_128<<<EW_BLOCKS, 256>>>(zbuf, src, dst, attn2);
    edge_exp<<<ET_BLOCKS, 256>>>(dst);
    edge_aggr_128<<<EW_BLOCKS, 256>>>(zbuf, src, dst, buf0);

    // ---- final GAT layer: relu(buf0) @ Wf -> zf [N,32]; aggregate -> outf
    gemm_k128<32, 2><<<GEMM_BLOCKS, 256>>>(buf0, Wf, zbuf, NN, 1);
    init_k<<<INITF_BLOCKS, 256>>>(outf, NN * 32, 1);
    edge_score_f<<<ET_BLOCKS, 256>>>(zbuf, src, dst, attnf);
    edge_exp<<<ET_BLOCKS, 256>>>(dst);
    edge_aggr_f<<<ET_BLOCKS, 256>>>(zbuf, src, dst, outf);

    // ---- head: mean over heads, graph pooling, MLP+BN+log_softmax
    pool_k<<<POOL_BLOCKS, 256>>>(outf, ng);
    mlp_k<<<1, 512>>>(mw1, gam, bet, mw2, (float*)d_out);

    (void)in_sizes; (void)n_in; (void)out_size;
}

// round 15
// speedup vs baseline: 1.0083x; 1.0015x over previous
#include <cuda_runtime.h>

// Problem constants (fixed by the reference)
#define NN 50000      // nodes
#define EE 800000     // edges
#define GG 32         // graphs
#define CC 16         // classes
#define NEG_SLOPE 0.2f
#define BN_EPS 1e-5f

// ---------------------------------------------------------------------------
// Scratch (static device globals; no allocation allowed)
// ---------------------------------------------------------------------------
__device__ float g_buf0[NN * 128];   // layer activations (ping)
__device__ float g_buf1[NN * 128];   // layer activations (pong)
__device__ float g_z[NN * 128];      // z = h @ W for current layer
__device__ float g_score[EE * 2];    // per-edge per-head score, then exp(score-max)
__device__ float g_denom[NN * 2];    // softmax denominators per dst,head
__device__ int   g_maxi[NN * 2];     // ordered-int encoded segment max per dst,head
__device__ float g_outf[NN * 32];    // final layer output [N,2,16]
__device__ float g_pooled[GG * CC];  // graph-pooled logits

// ---------------------------------------------------------------------------
// Helpers
// ---------------------------------------------------------------------------
__device__ __forceinline__ int f2o(float f) {           // order-preserving float->int
    int i = __float_as_int(f);
    return i >= 0 ? i : (i ^ 0x7fffffff);
}
__device__ __forceinline__ float o2f(int i) {
    return __int_as_float(i >= 0 ? i : (i ^ 0x7fffffff));
}
__device__ __forceinline__ float lrelu(float x) { return x > 0.f ? x : NEG_SLOPE * x; }

// ---------------------------------------------------------------------------
// Tiled SGEMM: Z[nrows, NC] = act(A[nrows,128]) @ W[128, NC]
// 128 rows per block, 256 threads, K chunked by 32 through shared memory.
// NC=128 (CPT=8) for hidden layers, NC=32 (CPT=2) for the final projection.
// relu_in != 0 applies ReLU to A while loading (layer activation fusion).
// ---------------------------------------------------------------------------
template <int NC, int CPT>
__global__ void __launch_bounds__(256)
gemm_k128(const float* __restrict__ A, const float* __restrict__ W,
          float* __restrict__ Z, int nrows, int relu_in)
{
    __shared__ float hs[128][33];     // padded to kill bank conflicts on a-loads
    __shared__ float Ws[32][NC];

    const int t  = threadIdx.x;
    const int tx = t & 15;            // column group
    const int ty = t >> 4;            // row group
    const int rowBase = blockIdx.x * 128;

    float acc[8][CPT];
#pragma unroll
    for (int i = 0; i < 8; i++)
#pragma unroll
        for (int j = 0; j < CPT; j++) acc[i][j] = 0.f;

#pragma unroll
    for (int kc = 0; kc < 4; kc++) {
        // --- stage A chunk: rows [rowBase, rowBase+128), cols [kc*32, kc*32+32)
#pragma unroll
        for (int q = 0; q < 4; q++) {
            int idx = t + q * 256;          // float4 index in [0,1024)
            int e   = idx * 4;
            int r   = e >> 5;               // 0..127
            int c   = e & 31;               // 0,4,...,28
            int gr  = rowBase + r;
            float4 v = make_float4(0.f, 0.f, 0.f, 0.f);
            if (gr < nrows)
                v = *reinterpret_cast<const float4*>(A + (size_t)gr * 128 + kc * 32 + c);
            if (relu_in) {
                v.x = fmaxf(v.x, 0.f); v.y = fmaxf(v.y, 0.f);
                v.z = fmaxf(v.z, 0.f); v.w = fmaxf(v.w, 0.f);
            }
            hs[r][c + 0] = v.x; hs[r][c + 1] = v.y;
            hs[r][c + 2] = v.z; hs[r][c + 3] = v.w;
        }
        // --- stage W chunk: rows [kc*32, kc*32+32), all NC cols
        constexpr int WV = (32 * NC) / 4;
#pragma unroll
        for (int idx = t; idx < WV; idx += 256) {
            int e = idx * 4;
            int r = e / NC;
            int c = e % NC;
            float4 v = *reinterpret_cast<const float4*>(W + (size_t)(kc * 32 + r) * NC + c);
            *reinterpret_cast<float4*>(&Ws[r][c]) = v;
        }
        __syncthreads();

#pragma unroll
        for (int k = 0; k < 32; k++) {
            float a[8], b[CPT];
#pragma unroll
            for (int i = 0; i < 8; i++) a[i] = hs[ty + 16 * i][k];
#pragma unroll
            for (int j = 0; j < CPT; j++) b[j] = Ws[k][tx + 16 * j];
#pragma unroll
            for (int i = 0; i < 8; i++)
#pragma unroll
                for (int j = 0; j < CPT; j++)
                    acc[i][j] = fmaf(a[i], b[j], acc[i][j]);
        }
        __syncthreads();
    }

#pragma unroll
    for (int i = 0; i < 8; i++) {
        int gr = rowBase + ty + 16 * i;
        if (gr < nrows) {
#pragma unroll
            for (int j = 0; j < CPT; j++)
                Z[(size_t)gr * NC + tx + 16 * j] = acc[i][j];
        }
    }
}

// ---------------------------------------------------------------------------
// Per-layer init: zero accumulation buffer, zero denominators, -inf segment max
// ---------------------------------------------------------------------------
__global__ void init_k(float* __restrict__ out, int nout, int zero_pooled)
{
    int idx = blockIdx.x * blockDim.x + threadIdx.x;
    if (idx < nout) out[idx] = 0.f;
    if (idx < NN * 2) { g_denom[idx] = 0.f; g_maxi[idx] = (int)0x80000000; }
    if (zero_pooled && idx < GG * CC) g_pooled[idx] = 0.f;
}

// ---------------------------------------------------------------------------
// Hidden layers (D=64, H=2): one warp per edge.
// Lanes 0..15 = head 0 dims, lanes 16..31 = head 1 dims (4 dims each).
// ---------------------------------------------------------------------------
__global__ void __launch_bounds__(256)
edge_score_128(const float* __restrict__ z, const int* __restrict__ src,
               const int* __restrict__ dst, const float* __restrict__ attn)
{
    int e = blockIdx.x * 8 + (threadIdx.x >> 5);
    if (e >= EE) return;
    int lane = threadIdx.x & 31;
    int s = __ldg(src + e), d = __ldg(dst + e);

    float4 zs = *reinterpret_cast<const float4*>(z + (size_t)s * 128 + lane * 4);
    float4 zd = *reinterpret_cast<const float4*>(z + (size_t)d * 128 + lane * 4);
    float4 at = *reinterpret_cast<const float4*>(attn + lane * 4);   // attn flat [128]

    float ex = lrelu(zs.x + zd.x);
    float ey = lrelu(zs.y + zd.y);
    float ez = lrelu(zs.z + zd.z);
    float ew = lrelu(zs.w + zd.w);
    float p = ex * at.x + ey * at.y + ez * at.z + ew * at.w;

    p += __shfl_xor_sync(0xffffffffu, p, 8);
    p += __shfl_xor_sync(0xffffffffu, p, 4);
    p += __shfl_xor_sync(0xffffffffu, p, 2);
    p += __shfl_xor_sync(0xffffffffu, p, 1);

    if ((lane & 15) == 0) {
        int h = lane >> 4;
        g_score[e * 2 + h] = p;
        atomicMax(&g_maxi[d * 2 + h], f2o(p));
    }
}

// exp(score - max) + denominator accumulation (shared by all layers)
__global__ void edge_exp(const int* __restrict__ dst)
{
    int idx = blockIdx.x * blockDim.x + threadIdx.x;
    if (idx >= EE * 2) return;
    int e = idx >> 1, h = idx & 1;
    int d = __ldg(dst + e);
    float m = o2f(g_maxi[d * 2 + h]);
    float a = __expf(g_score[idx] - m);
    g_score[idx] = a;
    atomicAdd(&g_denom[d * 2 + h], a);
}

__global__ void __launch_bounds__(256)
edge_aggr_128(const float* __restrict__ z, const int* __restrict__ src,
              const int* __restrict__ dst, float* __restrict__ out)
{
    int e = blockIdx.x * 8 + (threadIdx.x >> 5);
    if (e >= EE) return;
    int lane = threadIdx.x & 31;
    int s = __ldg(src + e), d = __ldg(dst + e);
    int h = lane >> 4;

    float den = g_denom[d * 2 + h];
    float alpha = g_score[e * 2 + h] / (den == 0.f ? 1.f : den);

    float4 zs = *reinterpret_cast<const float4*>(z + (size_t)s * 128 + lane * 4);
    float* o = out + (size_t)d * 128 + lane * 4;
    atomicAdd(o + 0, zs.x * alpha);
    atomicAdd(o + 1, zs.y * alpha);
    atomicAdd(o + 2, zs.z * alpha);
    atomicAdd(o + 3, zs.w * alpha);
}

// ---------------------------------------------------------------------------
// Final layer (C=16, H=2): one thread per (edge, head)
// ---------------------------------------------------------------------------
__global__ void edge_score_f(const float* __restrict__ z, const int* __restrict__ src,
                             const int* __restrict__ dst, const float* __restrict__ attnf)
{
    int idx = blockIdx.x * blockDim.x + threadIdx.x;
    if (idx >= EE * 2) return;
    int e = idx >> 1, h = idx & 1;
    int s = __ldg(src + e), d = __ldg(dst + e);

    const float4* zs = reinterpret_cast<const float4*>(z + (size_t)s * 32 + h * 16);
    const float4* zd = reinterpret_cast<const float4*>(z + (size_t)d * 32 + h * 16);
    const float4* at = reinterpret_cast<const float4*>(attnf + h * 16);

    float p = 0.f;
#pragma unroll
    for (int q = 0; q < 4; q++) {
        float4 a = zs[q], b = zd[q], w = at[q];
        p += lrelu(a.x + b.x) * w.x;
        p += lrelu(a.y + b.y) * w.y;
        p += lrelu(a.z + b.z) * w.z;
        p += lrelu(a.w + b.w) * w.w;
    }
    g_score[idx] = p;
    atomicMax(&g_maxi[d * 2 + h], f2o(p));
}

__global__ void edge_aggr_f(const float* __restrict__ z, const int* __restrict__ src,
                            const int* __restrict__ dst, float* __restrict__ outf)
{
    int idx = blockIdx.x * blockDim.x + threadIdx.x;
    if (idx >= EE * 2) return;
    int e = idx >> 1, h = idx & 1;
    int s = __ldg(src + e), d = __ldg(dst + e);

    float den = g_denom[d * 2 + h];
    float alpha = g_score[idx] / (den == 0.f ? 1.f : den);

    const float4* zs = reinterpret_cast<const float4*>(z + (size_t)s * 32 + h * 16);
    float* o = outf + (size_t)d * 32 + h * 16;
#pragma unroll
    for (int q = 0; q < 4; q++) {
        float4 v = zs[q];
        atomicAdd(o + q * 4 + 0, v.x * alpha);
        atomicAdd(o + q * 4 + 1, v.y * alpha);
        atomicAdd(o + q * 4 + 2, v.z * alpha);
        atomicAdd(o + q * 4 + 3, v.w * alpha);
    }
}

// Mean over heads + graph pooling (segment_sum by node_graph)
__global__ void pool_k(const float* __restrict__ outf, const int* __restrict__ ng)
{
    int idx = blockIdx.x * blockDim.x + threadIdx.x;
    if (idx >= NN * CC) return;
    int n = idx >> 4, c = idx & 15;
    float v = 0.5f * (outf[n * 32 + c] + outf[n * 32 + 16 + c]);
    atomicAdd(&g_pooled[__ldg(ng + n) * CC + c], v);
}

// ---------------------------------------------------------------------------
// Tiny MLP head: lin -> batchnorm(training stats) -> relu -> lin -> log_softmax
// Single block, 512 threads = (32 graphs x 16 classes).
// ---------------------------------------------------------------------------
__global__ void __launch_bounds__(512)
mlp_k(const float* __restrict__ w1, const float* __restrict__ gamma,
      const float* __restrict__ beta, const float* __restrict__ w2,
      float* __restrict__ out)
{
    __shared__ float P[GG][CC], H1[GG][CC], R[GG][CC], O[GG][CC];
    __shared__ float mu[CC], iv[CC];
    __shared__ float rm[GG], rl[GG];

    int t = threadIdx.x;
    int i = t >> 4, j = t & 15;

    P[i][j] = g_pooled[t];
    __syncthreads();

    float acc = 0.f;
#pragma unroll
    for (int k = 0; k < CC; k++) acc += P[i][k] * w1[k * CC + j];
    H1[i][j] = acc;
    __syncthreads();

    if (t < CC) {
        float m = 0.f;
        for (int r = 0; r < GG; r++) m += H1[r][t];
        m *= (1.f / GG);
        float v = 0.f;
        for (int r = 0; r < GG; r++) { float d = H1[r][t] - m; v += d * d; }
        v *= (1.f / GG);
        mu[t] = m;
        iv[t] = rsqrtf(v + BN_EPS);
    }
    __syncthreads();

    float hn = (H1[i][j] - mu[j]) * iv[j] * gamma[j] + beta[j];
    R[i][j] = fmaxf(hn, 0.f);
    __syncthreads();

    acc = 0.f;
#pragma unroll
    for (int k = 0; k < CC; k++) acc += R[i][k] * w2[k * CC + j];
    O[i][j] = acc;
    __syncthreads();

    if (j == 0) {
        float m = -1e30f;
        for (int k = 0; k < CC; k++) m = fmaxf(m, O[i][k]);
        float s = 0.f;
        for (int k = 0; k < CC; k++) s += __expf(O[i][k] - m);
        rm[i] = m;
        rl[i] = logf(s);
    }
    __syncthreads();

    out[t] = O[i][j] - rm[i] - rl[i];
}

// ---------------------------------------------------------------------------
// Host launch sequence (graph-capturable; kernel launches only)
// ---------------------------------------------------------------------------
extern "C" void kernel_launch(void* const* d_in, const int* in_sizes, int n_in,
                              void* d_out, int out_size)
{
    const float* feat  = (const float*)d_in[0];
    const float* W0    = (const float*)d_in[1];
    const float* attn0 = (const float*)d_in[2];
    const float* W1    = (const float*)d_in[3];
    const float* attn1 = (const float*)d_in[4];
    const float* W2    = (const float*)d_in[5];
    const float* attn2 = (const float*)d_in[6];
    const float* Wf    = (const float*)d_in[7];
    const float* attnf = (const float*)d_in[8];
    const float* mw1   = (const float*)d_in[9];
    const float* gam   = (const float*)d_in[10];
    const float* bet   = (const float*)d_in[11];
    const float* mw2   = (const float*)d_in[12];
    const int*   src   = (const int*)d_in[13];
    const int*   dst   = (const int*)d_in[14];
    const int*   ng    = (const int*)d_in[15];

    float *buf0, *buf1, *zbuf, *outf;
    cudaGetSymbolAddress((void**)&buf0, g_buf0);
    cudaGetSymbolAddress((void**)&buf1, g_buf1);
    cudaGetSymbolAddress((void**)&zbuf, g_z);
    cudaGetSymbolAddress((void**)&outf, g_outf);

    const int GEMM_BLOCKS = (NN + 127) / 128;          // 391
    const int EW_BLOCKS   = (EE + 7) / 8;              // warp-per-edge: 100000
    const int ET_BLOCKS   = (EE * 2 + 255) / 256;      // thread-per-(edge,head): 6250
    const int INIT_BLOCKS = (NN * 128 + 255) / 256;    // 25000
    const int INITF_BLOCKS= (NN * 32 + 255) / 256;     // 6250 (covers NN*2 too)
    const int POOL_BLOCKS = (NN * CC + 255) / 256;     // 3125

    // ---- layer 0: feat -> buf0
    gemm_k128<128, 8><<<GEMM_BLOCKS, 256>>>(feat, W0, zbuf, NN, 0);
    init_k<<<INIT_BLOCKS, 256>>>(buf0, NN * 128, 0);
    edge_score_128<<<EW_BLOCKS, 256>>>(zbuf, src, dst, attn0);
    edge_exp<<<ET_BLOCKS, 256>>>(dst);
    edge_aggr_128<<<EW_BLOCKS, 256>>>(zbuf, src, dst, buf0);

    // ---- layer 1: relu(buf0) -> buf1
    gemm_k128<128, 8><<<GEMM_BLOCKS, 256>>>(buf0, W1, zbuf, NN, 1);
    init_k<<<INIT_BLOCKS, 256>>>(buf1, NN * 128, 0);
    edge_score_128<<<EW_BLOCKS, 256>>>(zbuf, src, dst, attn1);
    edge_exp<<<ET_BLOCKS, 256>>>(dst);
    edge_aggr_128<<<EW_BLOCKS, 256>>>(zbuf, src, dst, buf1);

    // ---- layer 2: relu(buf1) -> buf0
    gemm_k128<128, 8><<<GEMM_BLOCKS, 256>>>(buf1, W2, zbuf, NN, 1);
    init_k<<<INIT_BLOCKS, 256>>>(buf0, NN * 128, 0);
    edge_score_128<<<EW_BLOCKS, 256>>>(zbuf, src, dst, attn2);
    edge_exp<<<ET_BLOCKS, 256>>>(dst);
    edge_aggr_128<<<EW_BLOCKS, 256>>>(zbuf, src, dst, buf0);

    // ---- final GAT layer: relu(buf0) @ Wf -> zf [N,32]; aggregate -> outf
    gemm_k128<32, 2><<<GEMM_BLOCKS, 256>>>(buf0, Wf, zbuf, NN, 1);
    init_k<<<INITF_BLOCKS, 256>>>(outf, NN * 32, 1);
    edge_score_f<<<ET_BLOCKS, 256>>>(zbuf, src, dst, attnf);
    edge_exp<<<ET_BLOCKS, 256>>>(dst);
    edge_aggr_f<<<ET_BLOCKS, 256>>>(zbuf, src, dst, outf);

    // ---- head: mean over heads, graph pooling, MLP+BN+log_softmax
    pool_k<<<POOL_BLOCKS, 256>>>(outf, ng);
    mlp_k<<<1, 512>>>(mw1, gam, bet, mw2, (float*)d_out);

    (void)in_sizes; (void)n_in; (void)out_size;
}

// round 16
// speedup vs baseline: 1.0114x; 1.0031x over previous
#include <cuda_runtime.h>

// Problem constants (fixed by the reference)
#define NN 50000      // nodes
#define EE 800000     // edges
#define GG 32         // graphs
#define CC 16         // classes
#define NEG_SLOPE 0.2f
#define BN_EPS 1e-5f

// ---------------------------------------------------------------------------
// Scratch (static device globals; no allocation allowed)
// ---------------------------------------------------------------------------
__device__ float g_buf0[NN * 128];   // layer activations (ping)
__device__ float g_buf1[NN * 128];   // layer activations (pong)
__device__ float g_z[NN * 128];      // z = h @ W for current layer
__device__ float g_score[EE * 2];    // per-edge per-head score, then exp(score-max)
__device__ float g_denom[NN * 2];    // softmax denominators per dst,head
__device__ int   g_maxi[NN * 2];     // ordered-int encoded segment max per dst,head
__device__ float g_outf[NN * 32];    // final layer output [N,2,16]
__device__ float g_pooled[GG * CC];  // graph-pooled logits

// ---------------------------------------------------------------------------
// Helpers
// ---------------------------------------------------------------------------
__device__ __forceinline__ int f2o(float f) {           // order-preserving float->int
    int i = __float_as_int(f);
    return i >= 0 ? i : (i ^ 0x7fffffff);
}
__device__ __forceinline__ float o2f(int i) {
    return __int_as_float(i >= 0 ? i : (i ^ 0x7fffffff));
}
__device__ __forceinline__ float lrelu(float x) { return x > 0.f ? x : NEG_SLOPE * x; }

// ---------------------------------------------------------------------------
// Tiled SGEMM: Z[nrows, NC] = act(A[nrows,128]) @ W[128, NC]
// 128 rows per block, 256 threads, K chunked by 32 through shared memory.
// NC=128 (CPT=8) for hidden layers, NC=32 (CPT=2) for the final projection.
// relu_in != 0 applies ReLU to A while loading (layer activation fusion).
// ---------------------------------------------------------------------------
template <int NC, int CPT>
__global__ void __launch_bounds__(256)
gemm_k128(const float* __restrict__ A, const float* __restrict__ W,
          float* __restrict__ Z, int nrows, int relu_in)
{
    __shared__ float hs[128][33];     // padded to kill bank conflicts on a-loads
    __shared__ float Ws[32][NC];

    const int t  = threadIdx.x;
    const int tx = t & 15;            // column group
    const int ty = t >> 4;            // row group
    const int rowBase = blockIdx.x * 128;

    float acc[8][CPT];
#pragma unroll
    for (int i = 0; i < 8; i++)
#pragma unroll
        for (int j = 0; j < CPT; j++) acc[i][j] = 0.f;

#pragma unroll
    for (int kc = 0; kc < 4; kc++) {
        // --- stage A chunk: rows [rowBase, rowBase+128), cols [kc*32, kc*32+32)
#pragma unroll
        for (int q = 0; q < 4; q++) {
            int idx = t + q * 256;          // float4 index in [0,1024)
            int e   = idx * 4;
            int r   = e >> 5;               // 0..127
            int c   = e & 31;               // 0,4,...,28
            int gr  = rowBase + r;
            float4 v = make_float4(0.f, 0.f, 0.f, 0.f);
            if (gr < nrows)
                v = *reinterpret_cast<const float4*>(A + (size_t)gr * 128 + kc * 32 + c);
            if (relu_in) {
                v.x = fmaxf(v.x, 0.f); v.y = fmaxf(v.y, 0.f);
                v.z = fmaxf(v.z, 0.f); v.w = fmaxf(v.w, 0.f);
            }
            hs[r][c + 0] = v.x; hs[r][c + 1] = v.y;
            hs[r][c + 2] = v.z; hs[r][c + 3] = v.w;
        }
        // --- stage W chunk: rows [kc*32, kc*32+32), all NC cols
        constexpr int WV = (32 * NC) / 4;
#pragma unroll
        for (int idx = t; idx < WV; idx += 256) {
            int e = idx * 4;
            int r = e / NC;
            int c = e % NC;
            float4 v = *reinterpret_cast<const float4*>(W + (size_t)(kc * 32 + r) * NC + c);
            *reinterpret_cast<float4*>(&Ws[r][c]) = v;
        }
        __syncthreads();

#pragma unroll
        for (int k = 0; k < 32; k++) {
            float a[8], b[CPT];
#pragma unroll
            for (int i = 0; i < 8; i++) a[i] = hs[ty + 16 * i][k];
#pragma unroll
            for (int j = 0; j < CPT; j++) b[j] = Ws[k][tx + 16 * j];
#pragma unroll
            for (int i = 0; i < 8; i++)
#pragma unroll
                for (int j = 0; j < CPT; j++)
                    acc[i][j] = fmaf(a[i], b[j], acc[i][j]);
        }
        __syncthreads();
    }

#pragma unroll
    for (int i = 0; i < 8; i++) {
        int gr = rowBase + ty + 16 * i;
        if (gr < nrows) {
#pragma unroll
            for (int j = 0; j < CPT; j++)
                Z[(size_t)gr * NC + tx + 16 * j] = acc[i][j];
        }
    }
}

// ---------------------------------------------------------------------------
// Per-layer init: zero accumulation buffer, zero denominators, -inf segment max
// ---------------------------------------------------------------------------
__global__ void init_k(float* __restrict__ out, int nout, int zero_pooled)
{
    int idx = blockIdx.x * blockDim.x + threadIdx.x;
    if (idx < nout) out[idx] = 0.f;
    if (idx < NN * 2) { g_denom[idx] = 0.f; g_maxi[idx] = (int)0x80000000; }
    if (zero_pooled && idx < GG * CC) g_pooled[idx] = 0.f;
}

// ---------------------------------------------------------------------------
// Hidden layers (D=64, H=2): one warp per edge.
// Lanes 0..15 = head 0 dims, lanes 16..31 = head 1 dims (4 dims each).
// ---------------------------------------------------------------------------
__global__ void __launch_bounds__(256)
edge_score_128(const float* __restrict__ z, const int* __restrict__ src,
               const int* __restrict__ dst, const float* __restrict__ attn)
{
    int e = blockIdx.x * 8 + (threadIdx.x >> 5);
    if (e >= EE) return;
    int lane = threadIdx.x & 31;
    int s = __ldg(src + e), d = __ldg(dst + e);

    float4 zs = *reinterpret_cast<const float4*>(z + (size_t)s * 128 + lane * 4);
    float4 zd = *reinterpret_cast<const float4*>(z + (size_t)d * 128 + lane * 4);
    float4 at = *reinterpret_cast<const float4*>(attn + lane * 4);   // attn flat [128]

    float ex = lrelu(zs.x + zd.x);
    float ey = lrelu(zs.y + zd.y);
    float ez = lrelu(zs.z + zd.z);
    float ew = lrelu(zs.w + zd.w);
    float p = ex * at.x + ey * at.y + ez * at.z + ew * at.w;

    p += __shfl_xor_sync(0xffffffffu, p, 8);
    p += __shfl_xor_sync(0xffffffffu, p, 4);
    p += __shfl_xor_sync(0xffffffffu, p, 2);
    p += __shfl_xor_sync(0xffffffffu, p, 1);

    if ((lane & 15) == 0) {
        int h = lane >> 4;
        g_score[e * 2 + h] = p;
        atomicMax(&g_maxi[d * 2 + h], f2o(p));
    }
}

// exp(score - max) + denominator accumulation (shared by all layers)
__global__ void edge_exp(const int* __restrict__ dst)
{
    int idx = blockIdx.x * blockDim.x + threadIdx.x;
    if (idx >= EE * 2) return;
    int e = idx >> 1, h = idx & 1;
    int d = __ldg(dst + e);
    float m = o2f(g_maxi[d * 2 + h]);
    float a = __expf(g_score[idx] - m);
    g_score[idx] = a;
    atomicAdd(&g_denom[d * 2 + h], a);
}

__global__ void __launch_bounds__(256)
edge_aggr_128(const float* __restrict__ z, const int* __restrict__ src,
              const int* __restrict__ dst, float* __restrict__ out)
{
    int e = blockIdx.x * 8 + (threadIdx.x >> 5);
    if (e >= EE) return;
    int lane = threadIdx.x & 31;
    int s = __ldg(src + e), d = __ldg(dst + e);
    int h = lane >> 4;

    float den = g_denom[d * 2 + h];
    float alpha = g_score[e * 2 + h] / (den == 0.f ? 1.f : den);

    float4 zs = *reinterpret_cast<const float4*>(z + (size_t)s * 128 + lane * 4);
    float* o = out + (size_t)d * 128 + lane * 4;
    atomicAdd(o + 0, zs.x * alpha);
    atomicAdd(o + 1, zs.y * alpha);
    atomicAdd(o + 2, zs.z * alpha);
    atomicAdd(o + 3, zs.w * alpha);
}

// ---------------------------------------------------------------------------
// Final layer (C=16, H=2): one thread per (edge, head)
// ---------------------------------------------------------------------------
__global__ void edge_score_f(const float* __restrict__ z, const int* __restrict__ src,
                             const int* __restrict__ dst, const float* __restrict__ attnf)
{
    int idx = blockIdx.x * blockDim.x + threadIdx.x;
    if (idx >= EE * 2) return;
    int e = idx >> 1, h = idx & 1;
    int s = __ldg(src + e), d = __ldg(dst + e);

    const float4* zs = reinterpret_cast<const float4*>(z + (size_t)s * 32 + h * 16);
    const float4* zd = reinterpret_cast<const float4*>(z + (size_t)d * 32 + h * 16);
    const float4* at = reinterpret_cast<const float4*>(attnf + h * 16);

    float p = 0.f;
#pragma unroll
    for (int q = 0; q < 4; q++) {
        float4 a = zs[q], b = zd[q], w = at[q];
        p += lrelu(a.x + b.x) * w.x;
        p += lrelu(a.y + b.y) * w.y;
        p += lrelu(a.z + b.z) * w.z;
        p += lrelu(a.w + b.w) * w.w;
    }
    g_score[idx] = p;
    atomicMax(&g_maxi[d * 2 + h], f2o(p));
}

__global__ void edge_aggr_f(const float* __restrict__ z, const int* __restrict__ src,
                            const int* __restrict__ dst, float* __restrict__ outf)
{
    int idx = blockIdx.x * blockDim.x + threadIdx.x;
    if (idx >= EE * 2) return;
    int e = idx >> 1, h = idx & 1;
    int s = __ldg(src + e), d = __ldg(dst + e);

    float den = g_denom[d * 2 + h];
    float alpha = g_score[idx] / (den == 0.f ? 1.f : den);

    const float4* zs = reinterpret_cast<const float4*>(z + (size_t)s * 32 + h * 16);
    float* o = outf + (size_t)d * 32 + h * 16;
#pragma unroll
    for (int q = 0; q < 4; q++) {
        float4 v = zs[q];
        atomicAdd(o + q * 4 + 0, v.x * alpha);
        atomicAdd(o + q * 4 + 1, v.y * alpha);
        atomicAdd(o + q * 4 + 2, v.z * alpha);
        atomicAdd(o + q * 4 + 3, v.w * alpha);
    }
}

// Mean over heads + graph pooling (segment_sum by node_graph)
__global__ void pool_k(const float* __restrict__ outf, const int* __restrict__ ng)
{
    int idx = blockIdx.x * blockDim.x + threadIdx.x;
    if (idx >= NN * CC) return;
    int n = idx >> 4, c = idx & 15;
    float v = 0.5f * (outf[n * 32 + c] + outf[n * 32 + 16 + c]);
    atomicAdd(&g_pooled[__ldg(ng + n) * CC + c], v);
}

// ---------------------------------------------------------------------------
// Tiny MLP head: lin -> batchnorm(training stats) -> relu -> lin -> log_softmax
// Single block, 512 threads = (32 graphs x 16 classes).
// ---------------------------------------------------------------------------
__global__ void __launch_bounds__(512)
mlp_k(const float* __restrict__ w1, const float* __restrict__ gamma,
      const float* __restrict__ beta, const float* __restrict__ w2,
      float* __restrict__ out)
{
    __shared__ float P[GG][CC], H1[GG][CC], R[GG][CC], O[GG][CC];
    __shared__ float mu[CC], iv[CC];
    __shared__ float rm[GG], rl[GG];

    int t = threadIdx.x;
    int i = t >> 4, j = t & 15;

    P[i][j] = g_pooled[t];
    __syncthreads();

    float acc = 0.f;
#pragma unroll
    for (int k = 0; k < CC; k++) acc += P[i][k] * w1[k * CC + j];
    H1[i][j] = acc;
    __syncthreads();

    if (t < CC) {
        float m = 0.f;
        for (int r = 0; r < GG; r++) m += H1[r][t];
        m *= (1.f / GG);
        float v = 0.f;
        for (int r = 0; r < GG; r++) { float d = H1[r][t] - m; v += d * d; }
        v *= (1.f / GG);
        mu[t] = m;
        iv[t] = rsqrtf(v + BN_EPS);
    }
    __syncthreads();

    float hn = (H1[i][j] - mu[j]) * iv[j] * gamma[j] + beta[j];
    R[i][j] = fmaxf(hn, 0.f);
    __syncthreads();

    acc = 0.f;
#pragma unroll
    for (int k = 0; k < CC; k++) acc += R[i][k] * w2[k * CC + j];
    O[i][j] = acc;
    __syncthreads();

    if (j == 0) {
        float m = -1e30f;
        for (int k = 0; k < CC; k++) m = fmaxf(m, O[i][k]);
        float s = 0.f;
        for (int k = 0; k < CC; k++) s += __expf(O[i][k] - m);
        rm[i] = m;
        rl[i] = logf(s);
    }
    __syncthreads();

    out[t] = O[i][j] - rm[i] - rl[i];
}

// ---------------------------------------------------------------------------
// Host launch sequence (graph-capturable; kernel launches only)
// ---------------------------------------------------------------------------
extern "C" void kernel_launch(void* const* d_in, const int* in_sizes, int n_in,
                              void* d_out, int out_size)
{
    const float* feat  = (const float*)d_in[0];
    const float* W0    = (const float*)d_in[1];
    const float* attn0 = (const float*)d_in[2];
    const float* W1    = (const float*)d_in[3];
    const float* attn1 = (const float*)d_in[4];
    const float* W2    = (const float*)d_in[5];
    const float* attn2 = (const float*)d_in[6];
    const float* Wf    = (const float*)d_in[7];
    const float* attnf = (const float*)d_in[8];
    const float* mw1   = (const float*)d_in[9];
    const float* gam   = (const float*)d_in[10];
    const float* bet   = (const float*)d_in[11];
    const float* mw2   = (const float*)d_in[12];
    const int*   src   = (const int*)d_in[13];
    const int*   dst   = (const int*)d_in[14];
    const int*   ng    = (const int*)d_in[15];

    float *buf0, *buf1, *zbuf, *outf;
    cudaGetSymbolAddress((void**)&buf0, g_buf0);
    cudaGetSymbolAddress((void**)&buf1, g_buf1);
    cudaGetSymbolAddress((void**)&zbuf, g_z);
    cudaGetSymbolAddress((void**)&outf, g_outf);

    const int GEMM_BLOCKS = (NN + 127) / 128;          // 391
    const int EW_BLOCKS   = (EE + 7) / 8;              // warp-per-edge: 100000
    const int ET_BLOCKS   = (EE * 2 + 255) / 256;      // thread-per-(edge,head): 6250
    const int INIT_BLOCKS = (NN * 128 + 255) / 256;    // 25000
    const int INITF_BLOCKS= (NN * 32 + 255) / 256;     // 6250 (covers NN*2 too)
    const int POOL_BLOCKS = (NN * CC + 255) / 256;     // 3125

    // ---- layer 0: feat -> buf0
    gemm_k128<128, 8><<<GEMM_BLOCKS, 256>>>(feat, W0, zbuf, NN, 0);
    init_k<<<INIT_BLOCKS, 256>>>(buf0, NN * 128, 0);
    edge_score_128<<<EW_BLOCKS, 256>>>(zbuf, src, dst, attn0);
    edge_exp<<<ET_BLOCKS, 256>>>(dst);
    edge_aggr_128<<<EW_BLOCKS, 256>>>(zbuf, src, dst, buf0);

    // ---- layer 1: relu(buf0) -> buf1
    gemm_k128<128, 8><<<GEMM_BLOCKS, 256>>>(buf0, W1, zbuf, NN, 1);
    init_k<<<INIT_BLOCKS, 256>>>(buf1, NN * 128, 0);
    edge_score_128<<<EW_BLOCKS, 256>>>(zbuf, src, dst, attn1);
    edge_exp<<<ET_BLOCKS, 256>>>(dst);
    edge_aggr_128<<<EW_BLOCKS, 256>>>(zbuf, src, dst, buf1);

    // ---- layer 2: relu(buf1) -> buf0
    gemm_k128<128, 8><<<GEMM_BLOCKS, 256>>>(buf1, W2, zbuf, NN, 1);
    init_k<<<INIT_BLOCKS, 256>>>(buf0, NN * 128, 0);
    edge_score_128<<<EW_BLOCKS, 256>>>(zbuf, src, dst, attn2);
    edge_exp<<<ET_BLOCKS, 256>>>(dst);
    edge_aggr_128<<<EW_BLOCKS, 256>>>(zbuf, src, dst, buf0);

    // ---- final GAT layer: relu(buf0) @ Wf -> zf [N,32]; aggregate -> outf
    gemm_k128<32, 2><<<GEMM_BLOCKS, 256>>>(buf0, Wf, zbuf, NN, 1);
    init_k<<<INITF_BLOCKS, 256>>>(outf, NN * 32, 1);
    edge_score_f<<<ET_BLOCKS, 256>>>(zbuf, src, dst, attnf);
    edge_exp<<<ET_BLOCKS, 256>>>(dst);
    edge_aggr_f<<<ET_BLOCKS, 256>>>(zbuf, src, dst, outf);

    // ---- head: mean over heads, graph pooling, MLP+BN+log_softmax
    pool_k<<<POOL_BLOCKS, 256>>>(outf, ng);
    mlp_k<<<1, 512>>>(mw1, gam, bet, mw2, (float*)d_out);

    (void)in_sizes; (void)n_in; (void)out_size;
}

// round 17
// speedup vs baseline: 2.7409x; 2.7099x over previous
#include <cuda_runtime.h>

// Problem constants (fixed by the reference)
#define NN 50000      // nodes
#define EE 800000     // edges
#define GG 32         // graphs
#define CC 16         // classes
#define NEG_SLOPE 0.2f
#define BN_EPS 1e-5f

// ---------------------------------------------------------------------------
// Scratch (static device globals; no allocation allowed)
// ---------------------------------------------------------------------------
__device__ float g_buf0[NN * 128];   // layer activations (ping)
__device__ float g_buf1[NN * 128];   // layer activations (pong)
__device__ float g_z[NN * 128];      // z = h @ W for current layer
__device__ int   g_cnt[NN];          // degree counts, then scatter cursor
__device__ int   g_rowptr[NN + 1];   // CSR row pointers (incoming edges per dst)
__device__ int   g_csrc[EE];         // src node ids grouped by dst
__device__ float g_pooled[GG * CC];  // graph-pooled logits

// ---------------------------------------------------------------------------
// Helpers
// ---------------------------------------------------------------------------
__device__ __forceinline__ float lrelu(float x) { return x > 0.f ? x : NEG_SLOPE * x; }

// ---------------------------------------------------------------------------
// Tiled SGEMM: Z[nrows, NC] = act(A[nrows,128]) @ W[128, NC]
// 128 rows per block, 256 threads, K chunked by 32 through shared memory.
// ---------------------------------------------------------------------------
template <int NC, int CPT>
__global__ void __launch_bounds__(256)
gemm_k128(const float* __restrict__ A, const float* __restrict__ W,
          float* __restrict__ Z, int nrows, int relu_in)
{
    __shared__ float hs[128][33];
    __shared__ float Ws[32][NC];

    const int t  = threadIdx.x;
    const int tx = t & 15;
    const int ty = t >> 4;
    const int rowBase = blockIdx.x * 128;

    float acc[8][CPT];
#pragma unroll
    for (int i = 0; i < 8; i++)
#pragma unroll
        for (int j = 0; j < CPT; j++) acc[i][j] = 0.f;

#pragma unroll
    for (int kc = 0; kc < 4; kc++) {
#pragma unroll
        for (int q = 0; q < 4; q++) {
            int idx = t + q * 256;
            int e   = idx * 4;
            int r   = e >> 5;
            int c   = e & 31;
            int gr  = rowBase + r;
            float4 v = make_float4(0.f, 0.f, 0.f, 0.f);
            if (gr < nrows)
                v = *reinterpret_cast<const float4*>(A + (size_t)gr * 128 + kc * 32 + c);
            if (relu_in) {
                v.x = fmaxf(v.x, 0.f); v.y = fmaxf(v.y, 0.f);
                v.z = fmaxf(v.z, 0.f); v.w = fmaxf(v.w, 0.f);
            }
            hs[r][c + 0] = v.x; hs[r][c + 1] = v.y;
            hs[r][c + 2] = v.z; hs[r][c + 3] = v.w;
        }
        constexpr int WV = (32 * NC) / 4;
#pragma unroll
        for (int idx = t; idx < WV; idx += 256) {
            int e = idx * 4;
            int r = e / NC;
            int c = e % NC;
            float4 v = *reinterpret_cast<const float4*>(W + (size_t)(kc * 32 + r) * NC + c);
            *reinterpret_cast<float4*>(&Ws[r][c]) = v;
        }
        __syncthreads();

#pragma unroll
        for (int k = 0; k < 32; k++) {
            float a[8], b[CPT];
#pragma unroll
            for (int i = 0; i < 8; i++) a[i] = hs[ty + 16 * i][k];
#pragma unroll
            for (int j = 0; j < CPT; j++) b[j] = Ws[k][tx + 16 * j];
#pragma unroll
            for (int i = 0; i < 8; i++)
#pragma unroll
                for (int j = 0; j < CPT; j++)
                    acc[i][j] = fmaf(a[i], b[j], acc[i][j]);
        }
        __syncthreads();
    }

#pragma unroll
    for (int i = 0; i < 8; i++) {
        int gr = rowBase + ty + 16 * i;
        if (gr < nrows) {
#pragma unroll
            for (int j = 0; j < CPT; j++)
                Z[(size_t)gr * NC + tx + 16 * j] = acc[i][j];
        }
    }
}

// ---------------------------------------------------------------------------
// CSR build (per launch; edges identical across layers)
// ---------------------------------------------------------------------------
__global__ void zero_cnt_k()
{
    int i = blockIdx.x * blockDim.x + threadIdx.x;
    if (i < NN) g_cnt[i] = 0;
    if (i < GG * CC) g_pooled[i] = 0.f;
}

__global__ void count_k(const int* __restrict__ dst)
{
    int e = blockIdx.x * blockDim.x + threadIdx.x;
    if (e < EE) atomicAdd(&g_cnt[__ldg(dst + e)], 1);
}

// Single-block inclusive scan over g_cnt -> g_rowptr[1..NN]; g_rowptr[0]=0.
__global__ void __launch_bounds__(1024) scan_k()
{
    __shared__ int wsum[32];
    __shared__ int carry_s;
    int t = threadIdx.x, lane = t & 31, wid = t >> 5;
    if (t == 0) { carry_s = 0; g_rowptr[0] = 0; }
    __syncthreads();
    for (int base = 0; base < NN; base += 1024) {
        int i = base + t;
        int x = (i < NN) ? g_cnt[i] : 0;
#pragma unroll
        for (int off = 1; off < 32; off <<= 1) {
            int y = __shfl_up_sync(0xffffffffu, x, off);
            if (lane >= off) x += y;
        }
        if (lane == 31) wsum[wid] = x;
        __syncthreads();
        if (wid == 0) {
            int w = wsum[lane];
#pragma unroll
            for (int off = 1; off < 32; off <<= 1) {
                int y = __shfl_up_sync(0xffffffffu, w, off);
                if (lane >= off) w += y;
            }
            wsum[lane] = w;
        }
        __syncthreads();
        int add = (wid > 0) ? wsum[wid - 1] : 0;
        int inc = x + add + carry_s;
        if (i < NN) g_rowptr[i + 1] = inc;
        __syncthreads();
        if (t == 1023) carry_s = inc;
        __syncthreads();
    }
}

__global__ void cursor_k()
{
    int i = blockIdx.x * blockDim.x + threadIdx.x;
    if (i < NN) g_cnt[i] = g_rowptr[i];
}

__global__ void scatter_k(const int* __restrict__ src, const int* __restrict__ dst)
{
    int e = blockIdx.x * blockDim.x + threadIdx.x;
    if (e >= EE) return;
    int pos = atomicAdd(&g_cnt[__ldg(dst + e)], 1);
    g_csrc[pos] = __ldg(src + e);
}

// ---------------------------------------------------------------------------
// Hidden GAT layer, dst-centric with online softmax. One warp per dst node.
// Lanes 0..15 = head 0 (4 dims each), lanes 16..31 = head 1.
// Single pass over incoming edges: no atomics, no score buffer, no init.
// ---------------------------------------------------------------------------
__global__ void __launch_bounds__(256)
gat_dst_128(const float* __restrict__ z, const float* __restrict__ attn,
            float* __restrict__ out)
{
    int n = blockIdx.x * 8 + (threadIdx.x >> 5);
    if (n >= NN) return;
    int lane = threadIdx.x & 31;

    int beg = __ldg(g_rowptr + n), end = __ldg(g_rowptr + n + 1);
    float4 zd = *reinterpret_cast<const float4*>(z + (size_t)n * 128 + lane * 4);
    float4 at = *reinterpret_cast<const float4*>(attn + lane * 4);

    float m = -3.4e38f, s = 0.f;
    float ax = 0.f, ay = 0.f, az = 0.f, aw = 0.f;

    for (int i = beg; i < end; i++) {
        int sidx = __ldg(g_csrc + i);
        float4 zs = *reinterpret_cast<const float4*>(z + (size_t)sidx * 128 + lane * 4);

        float p = lrelu(zs.x + zd.x) * at.x + lrelu(zs.y + zd.y) * at.y
                + lrelu(zs.z + zd.z) * at.z + lrelu(zs.w + zd.w) * at.w;
        p += __shfl_xor_sync(0xffffffffu, p, 8);
        p += __shfl_xor_sync(0xffffffffu, p, 4);
        p += __shfl_xor_sync(0xffffffffu, p, 2);
        p += __shfl_xor_sync(0xffffffffu, p, 1);
        // p = per-head score, identical across the 16 lanes of each head

        float nm = fmaxf(m, p);
        float sc = __expf(m - nm);     // m=-FLT_MAX first iter -> sc=0
        float w  = __expf(p - nm);
        s  = s  * sc + w;
        ax = ax * sc + w * zs.x;
        ay = ay * sc + w * zs.y;
        az = az * sc + w * zs.z;
        aw = aw * sc + w * zs.w;
        m  = nm;
    }

    float inv = (s > 0.f) ? (1.f / s) : 0.f;   // no incoming edges -> 0 output
    float4 o = make_float4(ax * inv, ay * inv, az * inv, aw * inv);
    *reinterpret_cast<float4*>(out + (size_t)n * 128 + lane * 4) = o;
}

// ---------------------------------------------------------------------------
// Final GAT layer (C=16, H=2) fused with head-mean + graph pooling.
// One warp per dst node; one float per lane (lane = h*16 + c).
// ---------------------------------------------------------------------------
__global__ void __launch_bounds__(256)
gat_dst_f(const float* __restrict__ z, const float* __restrict__ attnf,
          const int* __restrict__ ng)
{
    int n = blockIdx.x * 8 + (threadIdx.x >> 5);
    if (n >= NN) return;
    int lane = threadIdx.x & 31;

    int beg = __ldg(g_rowptr + n), end = __ldg(g_rowptr + n + 1);
    float zd = __ldg(z + (size_t)n * 32 + lane);
    float at = __ldg(attnf + lane);

    float m = -3.4e38f, s = 0.f, acc = 0.f;

    for (int i = beg; i < end; i++) {
        int sidx = __ldg(g_csrc + i);
        float zs = __ldg(z + (size_t)sidx * 32 + lane);

        float p = lrelu(zs + zd) * at;
        p += __shfl_xor_sync(0xffffffffu, p, 8);
        p += __shfl_xor_sync(0xffffffffu, p, 4);
        p += __shfl_xor_sync(0xffffffffu, p, 2);
        p += __shfl_xor_sync(0xffffffffu, p, 1);

        float nm = fmaxf(m, p);
        float sc = __expf(m - nm);
        float w  = __expf(p - nm);
        s   = s   * sc + w;
        acc = acc * sc + w * zs;
        m   = nm;
    }

    float inv = (s > 0.f) ? (1.f / s) : 0.f;
    float v = acc * inv;                             // logits[n][h][c]
    float u = __shfl_xor_sync(0xffffffffu, v, 16);   // other head, same c
    if (lane < 16)
        atomicAdd(&g_pooled[__ldg(ng + n) * CC + lane], 0.5f * (v + u));
}

// ---------------------------------------------------------------------------
// Tiny MLP head: lin -> batchnorm(training stats) -> relu -> lin -> log_softmax
// ---------------------------------------------------------------------------
__global__ void __launch_bounds__(512)
mlp_k(const float* __restrict__ w1, const float* __restrict__ gamma,
      const float* __restrict__ beta, const float* __restrict__ w2,
      float* __restrict__ out)
{
    __shared__ float P[GG][CC], H1[GG][CC], R[GG][CC], O[GG][CC];
    __shared__ float mu[CC], iv[CC];
    __shared__ float rm[GG], rl[GG];

    int t = threadIdx.x;
    int i = t >> 4, j = t & 15;

    P[i][j] = g_pooled[t];
    __syncthreads();

    float acc = 0.f;
#pragma unroll
    for (int k = 0; k < CC; k++) acc += P[i][k] * w1[k * CC + j];
    H1[i][j] = acc;
    __syncthreads();

    if (t < CC) {
        float m = 0.f;
        for (int r = 0; r < GG; r++) m += H1[r][t];
        m *= (1.f / GG);
        float v = 0.f;
        for (int r = 0; r < GG; r++) { float d = H1[r][t] - m; v += d * d; }
        v *= (1.f / GG);
        mu[t] = m;
        iv[t] = rsqrtf(v + BN_EPS);
    }
    __syncthreads();

    float hn = (H1[i][j] - mu[j]) * iv[j] * gamma[j] + beta[j];
    R[i][j] = fmaxf(hn, 0.f);
    __syncthreads();

    acc = 0.f;
#pragma unroll
    for (int k = 0; k < CC; k++) acc += R[i][k] * w2[k * CC + j];
    O[i][j] = acc;
    __syncthreads();

    if (j == 0) {
        float m = -1e30f;
        for (int k = 0; k < CC; k++) m = fmaxf(m, O[i][k]);
        float sum = 0.f;
        for (int k = 0; k < CC; k++) sum += __expf(O[i][k] - m);
        rm[i] = m;
        rl[i] = logf(sum);
    }
    __syncthreads();

    out[t] = O[i][j] - rm[i] - rl[i];
}

// ---------------------------------------------------------------------------
// Host launch sequence (graph-capturable; kernel launches only)
// ---------------------------------------------------------------------------
extern "C" void kernel_launch(void* const* d_in, const int* in_sizes, int n_in,
                              void* d_out, int out_size)
{
    const float* feat  = (const float*)d_in[0];
    const float* W0    = (const float*)d_in[1];
    const float* attn0 = (const float*)d_in[2];
    const float* W1    = (const float*)d_in[3];
    const float* attn1 = (const float*)d_in[4];
    const float* W2    = (const float*)d_in[5];
    const float* attn2 = (const float*)d_in[6];
    const float* Wf    = (const float*)d_in[7];
    const float* attnf = (const float*)d_in[8];
    const float* mw1   = (const float*)d_in[9];
    const float* gam   = (const float*)d_in[10];
    const float* bet   = (const float*)d_in[11];
    const float* mw2   = (const float*)d_in[12];
    const int*   src   = (const int*)d_in[13];
    const int*   dst   = (const int*)d_in[14];
    const int*   ng    = (const int*)d_in[15];

    float *buf0, *buf1, *zbuf;
    cudaGetSymbolAddress((void**)&buf0, g_buf0);
    cudaGetSymbolAddress((void**)&buf1, g_buf1);
    cudaGetSymbolAddress((void**)&zbuf, g_z);

    const int GEMM_BLOCKS = (NN + 127) / 128;     // 391
    const int NODE_BLOCKS = (NN + 7) / 8;         // warp-per-node: 6250
    const int NTH_BLOCKS  = (NN + 255) / 256;     // 196
    const int ETH_BLOCKS  = (EE + 255) / 256;     // 3125

    // ---- CSR build (edges identical for all layers) + zero pooled
    zero_cnt_k<<<NTH_BLOCKS, 256>>>();
    count_k<<<ETH_BLOCKS, 256>>>(dst);
    scan_k<<<1, 1024>>>();
    cursor_k<<<NTH_BLOCKS, 256>>>();
    scatter_k<<<ETH_BLOCKS, 256>>>(src, dst);

    // ---- layer 0: feat -> buf0
    gemm_k128<128, 8><<<GEMM_BLOCKS, 256>>>(feat, W0, zbuf, NN, 0);
    gat_dst_128<<<NODE_BLOCKS, 256>>>(zbuf, attn0, buf0);

    // ---- layer 1: relu(buf0) -> buf1
    gemm_k128<128, 8><<<GEMM_BLOCKS, 256>>>(buf0, W1, zbuf, NN, 1);
    gat_dst_128<<<NODE_BLOCKS, 256>>>(zbuf, attn1, buf1);

    // ---- layer 2: relu(buf1) -> buf0
    gemm_k128<128, 8><<<GEMM_BLOCKS, 256>>>(buf1, W2, zbuf, NN, 1);
    gat_dst_128<<<NODE_BLOCKS, 256>>>(zbuf, attn2, buf0);

    // ---- final GAT layer + fused head-mean + graph pooling
    gemm_k128<32, 2><<<GEMM_BLOCKS, 256>>>(buf0, Wf, zbuf, NN, 1);
    gat_dst_f<<<NODE_BLOCKS, 256>>>(zbuf, attnf, ng);

    // ---- MLP + BN + log_softmax
    mlp_k<<<1, 512>>>(mw1, gam, bet, mw2, (float*)d_out);

    (void)in_sizes; (void)n_in; (void)out_size;
}